// round 6
// baseline (speedup 1.0000x reference)
#include <cuda_runtime.h>
#include <cuda_bf16.h>
#include <cstdint>

// Problem constants
#define BB   128   // batch
#define SS   37    // sensors
#define TT   2048  // time steps
#define DD   256   // d_model
#define STT  8     // static feats
#define CC   2     // classes
#define MER  264   // merged = DD + STT
#define NF   74    // 2*SS features

#define NT   512        // threads per block
#define RF4  (TT / 4)   // 512 float4 per sensor row

// per-warp partial layout: 76 quantities x 4 partials, padded stride
#define PW   312        // floats per warp row (76*4=304, pad to 312)

// Phase-2 merge GEMV split: G i-groups x Q column-quads
#define G2   6
#define Q2   66              // 66*4 = 264 columns
#define KI2  (MER / G2)      // 44

__device__ __forceinline__ float wredf(float v) {
    #pragma unroll
    for (int o = 16; o; o >>= 1) v += __shfl_xor_sync(0xffffffffu, v, o);
    return v;
}

// 3-level reduction: lanes 0-3 end with 4 disjoint partial sums
__device__ __forceinline__ float wred3(float v) {
    v += __shfl_xor_sync(0xffffffffu, v, 16);
    v += __shfl_xor_sync(0xffffffffu, v, 8);
    v += __shfl_xor_sync(0xffffffffu, v, 4);
    return v;
}

__device__ __forceinline__ void pf_l2(const void* p) {
    asm volatile("prefetch.global.L2 [%0];" :: "l"(p));
}

__global__ __launch_bounds__(NT, 1)
void fused_kernel(const float* __restrict__ x,
                  const int*   __restrict__ smask,
                  const float* __restrict__ tim,
                  const float* __restrict__ stat,
                  const float* __restrict__ Ws,   // [NF, DD]
                  const float* __restrict__ bs,   // [DD]
                  const float* __restrict__ Wt,   // [1, DD]
                  const float* __restrict__ bt,   // [DD]
                  const float* __restrict__ Wst,  // [STT, STT]
                  const float* __restrict__ bst,  // [STT]
                  const float* __restrict__ Wm,   // [MER, MER]
                  const float* __restrict__ bm,   // [MER]
                  const float* __restrict__ Wc,   // [MER, CC]
                  const float* __restrict__ bc,   // [CC]
                  float* __restrict__ out) {
    const int b    = blockIdx.x;
    const int tid  = threadIdx.x;
    const int w    = tid >> 5;
    const int lane = tid & 31;

    __shared__ float  sW[16 * PW];      // per-warp partials [warp][76*4]
    __shared__ float  sAll[80];         // 74 feature sums + msum + tmsum
    __shared__ float  comb[MER];
    __shared__ float4 sH4[G2 * Q2];     // merge partials [g][q]
    __shared__ float  outc[CC];

    if (tid < CC) outc[tid] = 0.f;

    // ---- L2 prefetch of all weights (spread across the grid), fire-and-forget ----
    {
        unsigned r = (unsigned)b * NT + tid;
        const unsigned LWs = (NF * DD * 4) / 128;     // 592
        const unsigned LWm = (MER * MER * 4) / 128;   // 2178
        if (r < LWs) { pf_l2((const char*)Ws + r * 128u); }
        else { r -= LWs;
        if (r < LWm) { pf_l2((const char*)Wm + r * 128u); }
        else { r -= LWm;
        if (r < 17) { pf_l2((const char*)Wc + r * 128u); }
        else { r -= 17;
        if (r < 8) { pf_l2((const char*)bs + r * 128u); }
        else { r -= 8;
        if (r < 8) { pf_l2((const char*)bt + r * 128u); }
        else { r -= 8;
        if (r < 8) { pf_l2((const char*)Wt + r * 128u); }
        else { r -= 8;
        if (r < 9) { pf_l2((const char*)bm + r * 128u); }
        else { r -= 9;
        if (r < 32) { pf_l2((const char*)stat + r * 128u); }
        else { r -= 32;
        if (r < 2) { pf_l2((const char*)Wst + r * 128u); }
        else { r -= 2;
        if (r < 1) { pf_l2((const char*)bst); }
        else { r -= 1;
        if (r < 1) { pf_l2((const char*)bc); }
        }}}}}}}}}}
    }

    // ================= Phase 1: streaming reduction over [SS, TT] =================
    const size_t baseb = (size_t)b * SS * TT;
    const float4* __restrict__ xp = (const float4*)(x     + baseb) + tid;
    const int4*   __restrict__ mp = (const int4*)  (smask + baseb) + tid;

    const float4 tv = *((const float4*)(tim + (size_t)b * TT) + tid);

    float* myrow = &sW[w * PW];

    float fnz0 = 0.f, fnz1 = 0.f, fnz2 = 0.f, fnz3 = 0.f;
    int   inz0 = 0,   inz1 = 0,   inz2 = 0,   inz3 = 0;

    // -------- Pass A: x only (chunks of 8 sensors, double-buffered) --------
    {
        float4 buf[2][8];
        #pragma unroll
        for (int j = 0; j < 8; ++j) buf[0][j] = xp[j * RF4];

        #pragma unroll
        for (int c = 0; c < 5; ++c) {
            const int cur = c & 1, nxt = cur ^ 1;
            if (c < 4) {
                #pragma unroll
                for (int j = 0; j < 8; ++j) {
                    const int s = 8 * (c + 1) + j;
                    if (s < SS) buf[nxt][j] = xp[s * RF4];
                }
            }
            #pragma unroll
            for (int j = 0; j < 8; ++j) {
                const int s = 8 * c + j;
                if (s < SS) {
                    const float4 xv = buf[cur][j];
                    float ax = (xv.x + xv.y) + (xv.z + xv.w);
                    fnz0 += fabsf(xv.x);
                    fnz1 += fabsf(xv.y);
                    fnz2 += fabsf(xv.z);
                    fnz3 += fabsf(xv.w);
                    ax = wred3(ax);
                    if (lane < 4) myrow[s * 4 + lane] = ax;
                }
            }
        }
    }

    // -------- Pass B: mask only (chunks of 8 sensors, double-buffered) --------
    {
        int4 buf[2][8];
        #pragma unroll
        for (int j = 0; j < 8; ++j) buf[0][j] = mp[j * RF4];

        #pragma unroll
        for (int c = 0; c < 5; ++c) {
            const int cur = c & 1, nxt = cur ^ 1;
            if (c < 4) {
                #pragma unroll
                for (int j = 0; j < 8; ++j) {
                    const int s = 8 * (c + 1) + j;
                    if (s < SS) buf[nxt][j] = mp[s * RF4];
                }
            }
            #pragma unroll
            for (int j = 0; j < 8; ++j) {
                const int s = 8 * c + j;
                if (s < SS) {
                    const int4 mv = buf[cur][j];
                    float am = (float)((mv.x + mv.y) + (mv.z + mv.w));
                    inz0 += mv.x;
                    inz1 += mv.y;
                    inz2 += mv.z;
                    inz3 += mv.w;
                    am = wred3(am);
                    if (lane < 4) myrow[(SS + s) * 4 + lane] = am;
                }
            }
        }
    }

    // -------- mask count + masked time sum --------
    float ms = 0.f, tm = 0.f;
    if (fnz0 > 0.f || inz0 > 0) { ms += 1.f; tm += tv.x; }
    if (fnz1 > 0.f || inz1 > 0) { ms += 1.f; tm += tv.y; }
    if (fnz2 > 0.f || inz2 > 0) { ms += 1.f; tm += tv.z; }
    if (fnz3 > 0.f || inz3 > 0) { ms += 1.f; tm += tv.w; }
    ms = wred3(ms);
    tm = wred3(tm);
    if (lane < 4) {
        myrow[74 * 4 + lane] = ms;
        myrow[75 * 4 + lane] = tm;
    }
    __syncthreads();

    // -------- final combine: 76 outputs, 64 partials each (float4 LDS) --------
    if (tid < 76) {
        float acc = 0.f;
        #pragma unroll
        for (int w2 = 0; w2 < 16; ++w2) {
            const float4 p = *(const float4*)&sW[w2 * PW + tid * 4];
            acc += (p.x + p.y) + (p.z + p.w);
        }
        sAll[tid] = acc;
    }
    __syncthreads();

    // ================= Phase 2: per-batch tail (L2-warm) =================
    const float msum  = sAll[74];
    const float tmsum = sAll[75];
    const float inv   = 1.f / fmaxf(msum, 1e-9f);

    // ---- Phase A: comb[MER] ----
    if (tid < DD) {
        float acc = 0.f;
        #pragma unroll
        for (int f = 0; f < NF; ++f) acc += sAll[f] * Ws[f * DD + tid];
        acc += msum * (bs[tid] + bt[tid]) + tmsum * Wt[tid];
        comb[tid] = acc * inv;
    } else if (tid < MER) {
        const int j = tid - DD;
        float acc = bst[j];
        #pragma unroll
        for (int i = 0; i < STT; ++i) acc += stat[b * STT + i] * Wst[i * STT + j];
        comb[tid] = acc;
    }
    __syncthreads();

    // ---- Phase B: merge GEMV, split-i (G2 groups), float4 columns ----
    if (tid < G2 * Q2) {
        const int q  = tid % Q2;   // column quad
        const int gg = tid / Q2;   // i-group
        const float4* __restrict__ Wm4 = (const float4*)Wm;  // row = 66 quads
        float4 acc = make_float4(0.f, 0.f, 0.f, 0.f);
        #pragma unroll
        for (int k = 0; k < KI2; ++k) {
            const int i = gg * KI2 + k;
            const float  c  = comb[i];
            const float4 wv = Wm4[i * Q2 + q];
            acc.x += c * wv.x;
            acc.y += c * wv.y;
            acc.z += c * wv.z;
            acc.w += c * wv.w;
        }
        sH4[gg * Q2 + q] = acc;
    }
    __syncthreads();

    // ---- Phase C: reduce partials, ReLU, classifier ----
    float p0 = 0.f, p1 = 0.f;
    if (tid < MER) {
        const float* sH = (const float*)sH4;   // [g][264]
        float t = bm[tid];
        #pragma unroll
        for (int gg = 0; gg < G2; ++gg) t += sH[gg * MER + tid];
        const float h = fmaxf(t, 0.f);
        p0 = h * Wc[tid * CC + 0];
        p1 = h * Wc[tid * CC + 1];
    }
    p0 = wredf(p0);
    p1 = wredf(p1);
    if (lane == 0) {
        atomicAdd(&outc[0], p0);
        atomicAdd(&outc[1], p1);
    }
    __syncthreads();

    if (tid < CC) out[b * CC + tid] = outc[tid] + bc[tid];
}

// ---------------- launch ----------------
extern "C" void kernel_launch(void* const* d_in, const int* in_sizes, int n_in,
                              void* d_out, int out_size) {
    const float* x     = (const float*)d_in[0];
    const float* stat  = (const float*)d_in[1];
    const float* tim   = (const float*)d_in[2];
    const int*   smask = (const int*)  d_in[3];
    const float* Ws    = (const float*)d_in[4];
    const float* bs    = (const float*)d_in[5];
    const float* Wt    = (const float*)d_in[6];
    const float* bt    = (const float*)d_in[7];
    const float* Wst   = (const float*)d_in[8];
    const float* bst   = (const float*)d_in[9];
    const float* Wm    = (const float*)d_in[10];
    const float* bm    = (const float*)d_in[11];
    const float* Wc    = (const float*)d_in[12];
    const float* bc    = (const float*)d_in[13];
    float* out = (float*)d_out;

    fused_kernel<<<BB, NT>>>(x, smask, tim, stat, Ws, bs, Wt, bt,
                             Wst, bst, Wm, bm, Wc, bc, out);
}